// round 5
// baseline (speedup 1.0000x reference)
#include <cuda_runtime.h>
#include <math.h>

#define Bn    16
#define Hn    512
#define Wn    512
#define HWn   (Hn * Wn)
#define NPIX  (Bn * HWn)

// localvar tile: 32x32 outputs, halo 3, smem rows span cols tx0-4..tx0+35
#define TW    32
#define TH    32
#define EXTH  38
#define SRS   40   // s_r row stride
#define HSS   36   // h-sum row stride

#define RBLK  4096 // residual blocks (1024 px, 256/image)
#define LBLK  4096 // localvar blocks (16 x 16 x 16)

// Scratch (__device__ globals; rewritten every call)
__device__ float g_rsr[NPIX];                 // signed: sign bit = gate off
__device__ float g_psum[RBLK], g_psq[RBLK];   // residual per-block partials
__device__ float g_pS[LBLK];                  // localvar per-block partials

__device__ __forceinline__ float warpRed(float v) {
    #pragma unroll
    for (int o = 16; o; o >>= 1) v += __shfl_down_sync(0xffffffffu, v, o);
    return v;
}
__device__ __forceinline__ double warpRedD(double v) {
    #pragma unroll
    for (int o = 16; o; o >>= 1) v += __shfl_down_sync(0xffffffffu, v, o);
    return v;
}
__device__ __forceinline__ int refl(int i) {
    i = (i < 0) ? -i : i;
    return (i >= Hn) ? (2 * (Hn - 1) - i) : i;
}

// ---------------------------------------------------------------------------
// Residual: rs = sum_c |gt-out|; gate vs sum_c |gt-ema| folded into sign bit;
// per-block sum/sumsq partials. float4 throughout. At the HBM roof.
// ---------------------------------------------------------------------------
__global__ __launch_bounds__(256) void k_residual(const float* __restrict__ outp,
                                                  const float* __restrict__ emap,
                                                  const float* __restrict__ gtp) {
    int blk = blockIdx.x;
    int b   = blk >> 8;
    int p   = (blk & 255) * 1024 + threadIdx.x * 4;
    size_t base = (size_t)b * 3 * HWn + p;

    float4 g0 = *(const float4*)(gtp  + base);
    float4 g1 = *(const float4*)(gtp  + base + HWn);
    float4 g2 = *(const float4*)(gtp  + base + 2 * HWn);
    float4 o0 = *(const float4*)(outp + base);
    float4 o1 = *(const float4*)(outp + base + HWn);
    float4 o2 = *(const float4*)(outp + base + 2 * HWn);
    float4 e0 = *(const float4*)(emap + base);
    float4 e1 = *(const float4*)(emap + base + HWn);
    float4 e2 = *(const float4*)(emap + base + 2 * HWn);

    float4 rs, re;
    rs.x = fabsf(g0.x-o0.x)+fabsf(g1.x-o1.x)+fabsf(g2.x-o2.x);
    rs.y = fabsf(g0.y-o0.y)+fabsf(g1.y-o1.y)+fabsf(g2.y-o2.y);
    rs.z = fabsf(g0.z-o0.z)+fabsf(g1.z-o1.z)+fabsf(g2.z-o2.z);
    rs.w = fabsf(g0.w-o0.w)+fabsf(g1.w-o1.w)+fabsf(g2.w-o2.w);
    re.x = fabsf(g0.x-e0.x)+fabsf(g1.x-e1.x)+fabsf(g2.x-e2.x);
    re.y = fabsf(g0.y-e0.y)+fabsf(g1.y-e1.y)+fabsf(g2.y-e2.y);
    re.z = fabsf(g0.z-e0.z)+fabsf(g1.z-e1.z)+fabsf(g2.z-e2.z);
    re.w = fabsf(g0.w-e0.w)+fabsf(g1.w-e1.w)+fabsf(g2.w-e2.w);

    float4 sv;   // sign bit encodes gate (negative => gated off)
    sv.x = (rs.x < re.x) ? -rs.x : rs.x;
    sv.y = (rs.y < re.y) ? -rs.y : rs.y;
    sv.z = (rs.z < re.z) ? -rs.z : rs.z;
    sv.w = (rs.w < re.w) ? -rs.w : rs.w;
    *(float4*)(g_rsr + (size_t)b * HWn + p) = sv;

    float lsum = rs.x + rs.y + rs.z + rs.w;
    float lsq  = rs.x*rs.x + rs.y*rs.y + rs.z*rs.z + rs.w*rs.w;

    lsum = warpRed(lsum); lsq = warpRed(lsq);
    __shared__ float sh_s[8], sh_q[8];
    int lane = threadIdx.x & 31, w = threadIdx.x >> 5;
    if (lane == 0) { sh_s[w] = lsum; sh_q[w] = lsq; }
    __syncthreads();
    if (w == 0) {
        lsum = (lane < 8) ? sh_s[lane] : 0.f;
        lsq  = (lane < 8) ? sh_q[lane] : 0.f;
        lsum = warpRed(lsum); lsq = warpRed(lsq);
        if (lane == 0) { g_psum[blk] = lsum; g_psq[blk] = lsq; }
    }
}

// ---------------------------------------------------------------------------
// Separable 7x7 unbiased local variance (reflect pad) + gated loss partial.
// 32x32 tile, ~17 KB smem (8 blocks/SM), sliding windows both directions.
// ---------------------------------------------------------------------------
__global__ __launch_bounds__(256) void k_localvar() {
    __shared__ float s_r [EXTH * SRS];   // signed rs, cols tx0-4..tx0+35
    __shared__ float s_hs[EXTH * HSS];   // horizontal 7-sum of |rs|
    __shared__ float s_hq[EXTH * HSS];   // horizontal 7-sum of rs^2
    __shared__ float sh[8];

    int b   = blockIdx.z;
    int tx0 = blockIdx.x * TW;
    int ty0 = blockIdx.y * TH;
    int tid = threadIdx.x;

    const float* rb = g_rsr + (size_t)b * HWn;
    bool edge = (tx0 == 0) || (ty0 == 0) || (tx0 + TW == Wn) || (ty0 + TH == Hn);

    // Phase 1: load signed-rs halo tile (float4 for interior blocks).
    if (!edge) {
        for (int i = tid; i < EXTH * 10; i += 256) {
            int lr = i / 10, lc4 = (i - lr * 10) * 4;
            float4 v = *(const float4*)(rb + (ty0 + lr - 3) * Wn + (tx0 - 4) + lc4);
            *(float4*)&s_r[lr * SRS + lc4] = v;
        }
    } else {
        for (int i = tid; i < EXTH * SRS; i += 256) {
            int lr = i / SRS, lc = i - lr * SRS;
            s_r[lr * SRS + lc] = rb[refl(ty0 + lr - 3) * Wn + refl(tx0 - 4 + lc)];
        }
    }
    __syncthreads();

    // Phase 2: horizontal 7-taps, 4 outputs/thread, aligned float4 LDS.
    // Output col c uses smem cols c+1..c+7; group g4 reads g4..g4+11.
    for (int i = tid; i < EXTH * (TW / 4); i += 256) {
        int row = i >> 3;
        int g4  = (i & 7) << 2;
        const float* rp = &s_r[row * SRS + g4];
        float4 A = *(const float4*)(rp);
        float4 Bv = *(const float4*)(rp + 4);
        float4 Cv = *(const float4*)(rp + 8);
        float v0 = fabsf(A.y), v1 = fabsf(A.z), v2 = fabsf(A.w);
        float v3 = fabsf(Bv.x), v4 = fabsf(Bv.y), v5 = fabsf(Bv.z), v6 = fabsf(Bv.w);
        float v7 = fabsf(Cv.x), v8 = fabsf(Cv.y), v9 = fabsf(Cv.z);
        float s0 = v0+v1+v2+v3+v4+v5+v6;
        float s1 = s0 - v0 + v7;
        float s2 = s1 - v1 + v8;
        float s3 = s2 - v2 + v9;
        float q0 = v0*v0+v1*v1+v2*v2+v3*v3+v4*v4+v5*v5+v6*v6;
        float q1 = q0 + (v7*v7 - v0*v0);
        float q2 = q1 + (v8*v8 - v1*v1);
        float q3 = q2 + (v9*v9 - v2*v2);
        *(float4*)&s_hs[row * HSS + g4] = make_float4(s0, s1, s2, s3);
        *(float4*)&s_hq[row * HSS + g4] = make_float4(q0, q1, q2, q3);
    }
    __syncthreads();

    // Phase 3: vertical 7-taps, register sliding window, 4 rows/thread.
    int c  = tid & (TW - 1);
    int r0 = (tid >> 5) * 4;
    float s = 0.f, q = 0.f;
    #pragma unroll
    for (int d = 0; d < 7; d++) {
        s += s_hs[(r0 + d) * HSS + c];
        q += s_hq[(r0 + d) * HSS + c];
    }
    float acc = 0.f;
    #pragma unroll
    for (int k = 0; k < 4; k++) {
        int r = r0 + k;
        float var = (q - s * s * (1.f / 49.f)) * (1.f / 48.f);
        float raw = s_r[(r + 3) * SRS + c + 4];
        if (!(__float_as_uint(raw) >> 31))     // gate = sign bit clear
            acc += fabsf(var) * raw;           // raw >= 0 here
        if (k < 3) {
            s += s_hs[(r + 7) * HSS + c] - s_hs[r * HSS + c];
            q += s_hq[(r + 7) * HSS + c] - s_hq[r * HSS + c];
        }
    }

    acc = warpRed(acc);
    int lane = tid & 31, w = tid >> 5;
    if (lane == 0) sh[w] = acc;
    __syncthreads();
    if (w == 0) {
        acc = (lane < 8) ? sh[lane] : 0.f;
        acc = warpRed(acc);
        if (lane == 0)
            g_pS[(blockIdx.z * 16 + blockIdx.y) * 16 + blockIdx.x] = acc;
    }
}

// ---------------------------------------------------------------------------
// Final: per-image var -> var^0.2, loss = sum_b pw_b*S_b / (B*3*H*W).
// One block, 16 warps; warp b handles image b in double precision.
// ---------------------------------------------------------------------------
__global__ void k_final(float* out) {
    __shared__ double shd[16];
    int lane = threadIdx.x & 31, b = threadIdx.x >> 5;   // 512 threads
    double s = 0.0, q = 0.0, S = 0.0;
    for (int j = lane; j < 256; j += 32) {
        s += (double)g_psum[b * 256 + j];
        q += (double)g_psq [b * 256 + j];
        S += (double)g_pS  [b * 256 + j];
    }
    s = warpRedD(s); q = warpRedD(q); S = warpRedD(S);
    if (lane == 0) {
        double n   = (double)HWn;
        double var = (q - s * s / n) / (n - 1.0);
        shd[b] = pow(var, 0.2) * S;
    }
    __syncthreads();
    if (threadIdx.x == 0) {
        double tot = 0.0;
        #pragma unroll
        for (int i = 0; i < 16; i++) tot += shd[i];
        out[0] = (float)(tot / (double)((long long)Bn * 3 * HWn));
    }
}

extern "C" void kernel_launch(void* const* d_in, const int* in_sizes, int n_in,
                              void* d_out, int out_size) {
    const float* outp = (const float*)d_in[0];
    const float* emap = (const float*)d_in[1];
    const float* gtp  = (const float*)d_in[2];
    float* out = (float*)d_out;

    k_residual<<<RBLK, 256>>>(outp, emap, gtp);
    dim3 grid(Wn / TW, Hn / TH, Bn);
    k_localvar<<<grid, 256>>>();
    k_final<<<1, 512>>>(out);
}

// round 6
// speedup vs baseline: 1.0275x; 1.0275x over previous
#include <cuda_runtime.h>
#include <math.h>

#define Bn    16
#define Hn    512
#define Wn    512
#define HWn   (Hn * Wn)
#define NPIX  (Bn * HWn)

#define TW    32
#define TH    32
#define EXTH  38
#define HSS   36   // h-sum row stride (floats)

#define RBLK  4096 // residual blocks (1024 px, 256/image)
#define LBLK  4096 // localvar blocks (16 x 16 x 16)

// Scratch (__device__ globals; rewritten every call)
__device__ float g_rsr[NPIX];                 // signed: sign bit = gate off
__device__ float g_psum[RBLK], g_psq[RBLK];   // residual per-block partials
__device__ float g_pS[LBLK];                  // localvar per-block partials

__device__ __forceinline__ float warpRed(float v) {
    #pragma unroll
    for (int o = 16; o; o >>= 1) v += __shfl_down_sync(0xffffffffu, v, o);
    return v;
}
__device__ __forceinline__ double warpRedD(double v) {
    #pragma unroll
    for (int o = 16; o; o >>= 1) v += __shfl_down_sync(0xffffffffu, v, o);
    return v;
}
__device__ __forceinline__ int refl(int i) {
    i = (i < 0) ? -i : i;
    return (i >= Hn) ? (2 * (Hn - 1) - i) : i;
}

// ---------------------------------------------------------------------------
// Residual: rs = sum_c |gt-out|; gate vs sum_c |gt-ema| folded into sign bit;
// per-block sum/sumsq partials. float4 throughout. At the HBM roof (~27us).
// ---------------------------------------------------------------------------
__global__ __launch_bounds__(256) void k_residual(const float* __restrict__ outp,
                                                  const float* __restrict__ emap,
                                                  const float* __restrict__ gtp) {
    int blk = blockIdx.x;
    int b   = blk >> 8;
    int p   = (blk & 255) * 1024 + threadIdx.x * 4;
    size_t base = (size_t)b * 3 * HWn + p;

    float4 g0 = *(const float4*)(gtp  + base);
    float4 g1 = *(const float4*)(gtp  + base + HWn);
    float4 g2 = *(const float4*)(gtp  + base + 2 * HWn);
    float4 o0 = *(const float4*)(outp + base);
    float4 o1 = *(const float4*)(outp + base + HWn);
    float4 o2 = *(const float4*)(outp + base + 2 * HWn);
    float4 e0 = *(const float4*)(emap + base);
    float4 e1 = *(const float4*)(emap + base + HWn);
    float4 e2 = *(const float4*)(emap + base + 2 * HWn);

    float4 rs, re;
    rs.x = fabsf(g0.x-o0.x)+fabsf(g1.x-o1.x)+fabsf(g2.x-o2.x);
    rs.y = fabsf(g0.y-o0.y)+fabsf(g1.y-o1.y)+fabsf(g2.y-o2.y);
    rs.z = fabsf(g0.z-o0.z)+fabsf(g1.z-o1.z)+fabsf(g2.z-o2.z);
    rs.w = fabsf(g0.w-o0.w)+fabsf(g1.w-o1.w)+fabsf(g2.w-o2.w);
    re.x = fabsf(g0.x-e0.x)+fabsf(g1.x-e1.x)+fabsf(g2.x-e2.x);
    re.y = fabsf(g0.y-e0.y)+fabsf(g1.y-e1.y)+fabsf(g2.y-e2.y);
    re.z = fabsf(g0.z-e0.z)+fabsf(g1.z-e1.z)+fabsf(g2.z-e2.z);
    re.w = fabsf(g0.w-e0.w)+fabsf(g1.w-e1.w)+fabsf(g2.w-e2.w);

    float4 sv;   // sign bit encodes gate (negative => gated off)
    sv.x = (rs.x < re.x) ? -rs.x : rs.x;
    sv.y = (rs.y < re.y) ? -rs.y : rs.y;
    sv.z = (rs.z < re.z) ? -rs.z : rs.z;
    sv.w = (rs.w < re.w) ? -rs.w : rs.w;
    *(float4*)(g_rsr + (size_t)b * HWn + p) = sv;

    float lsum = rs.x + rs.y + rs.z + rs.w;
    float lsq  = rs.x*rs.x + rs.y*rs.y + rs.z*rs.z + rs.w*rs.w;

    lsum = warpRed(lsum); lsq = warpRed(lsq);
    __shared__ float sh_s[8], sh_q[8];
    int lane = threadIdx.x & 31, w = threadIdx.x >> 5;
    if (lane == 0) { sh_s[w] = lsum; sh_q[w] = lsq; }
    __syncthreads();
    if (w == 0) {
        lsum = (lane < 8) ? sh_s[lane] : 0.f;
        lsq  = (lane < 8) ? sh_q[lane] : 0.f;
        lsum = warpRed(lsum); lsq = warpRed(lsq);
        if (lane == 0) { g_psum[blk] = lsum; g_psq[blk] = lsq; }
    }
}

// ---------------------------------------------------------------------------
// 7x7 unbiased local variance (reflect) + gated loss partial.
// Horizontal taps computed straight from GMEM (L1/L2 absorbs the 2.4x column
// overlap); only h-sums staged in smem; one barrier; center rs re-read via LDG.
// ---------------------------------------------------------------------------
__global__ __launch_bounds__(256, 8) void k_localvar() {
    __shared__ float s_hs[EXTH * HSS];   // horizontal 7-sum of |rs|
    __shared__ float s_hq[EXTH * HSS];   // horizontal 7-sum of rs^2
    __shared__ float sh[8];

    int b   = blockIdx.z;
    int tx0 = blockIdx.x * TW;
    int ty0 = blockIdx.y * TH;
    int tid = threadIdx.x;

    const float* rb = g_rsr + (size_t)b * HWn;

    // Phase A: horizontal 7-taps from GMEM. 38 rows x 8 groups of 4 outputs.
    for (int i = tid; i < EXTH * 8; i += 256) {
        int row = i >> 3;
        int g4  = (i & 7) << 2;
        int gr  = refl(ty0 + row - 3);           // row reflect (free)
        const float* rowp = rb + gr * Wn;
        int cb = tx0 + g4 - 4;                   // first col of aligned 12-window
        float v0, v1, v2, v3, v4, v5, v6, v7, v8, v9;
        if (cb >= 0 && cb + 11 < Wn) {           // interior columns (fast path)
            float4 A  = *(const float4*)(rowp + cb);
            float4 Bv = *(const float4*)(rowp + cb + 4);
            float4 Cv = *(const float4*)(rowp + cb + 8);
            v0 = fabsf(A.y);  v1 = fabsf(A.z);  v2 = fabsf(A.w);
            v3 = fabsf(Bv.x); v4 = fabsf(Bv.y); v5 = fabsf(Bv.z); v6 = fabsf(Bv.w);
            v7 = fabsf(Cv.x); v8 = fabsf(Cv.y); v9 = fabsf(Cv.z);
        } else {                                  // image border: reflect cols
            v0 = fabsf(rowp[refl(cb + 1)]);
            v1 = fabsf(rowp[refl(cb + 2)]);
            v2 = fabsf(rowp[refl(cb + 3)]);
            v3 = fabsf(rowp[refl(cb + 4)]);
            v4 = fabsf(rowp[refl(cb + 5)]);
            v5 = fabsf(rowp[refl(cb + 6)]);
            v6 = fabsf(rowp[refl(cb + 7)]);
            v7 = fabsf(rowp[refl(cb + 8)]);
            v8 = fabsf(rowp[refl(cb + 9)]);
            v9 = fabsf(rowp[refl(cb + 10)]);
        }
        float s0 = v0+v1+v2+v3+v4+v5+v6;
        float s1 = s0 - v0 + v7;
        float s2 = s1 - v1 + v8;
        float s3 = s2 - v2 + v9;
        float q0 = v0*v0+v1*v1+v2*v2+v3*v3+v4*v4+v5*v5+v6*v6;
        float q1 = q0 + (v7*v7 - v0*v0);
        float q2 = q1 + (v8*v8 - v1*v1);
        float q3 = q2 + (v9*v9 - v2*v2);
        *(float4*)&s_hs[row * HSS + g4] = make_float4(s0, s1, s2, s3);
        *(float4*)&s_hq[row * HSS + g4] = make_float4(q0, q1, q2, q3);
    }
    __syncthreads();

    // Phase B: vertical 7-taps (register sliding window, 4 rows/thread);
    // center rs via coalesced LDG (L2-hot); gate = sign bit.
    int c  = tid & 31;
    int r0 = (tid >> 5) * 4;
    float s = 0.f, q = 0.f;
    #pragma unroll
    for (int d = 0; d < 7; d++) {
        s += s_hs[(r0 + d) * HSS + c];
        q += s_hq[(r0 + d) * HSS + c];
    }
    float acc = 0.f;
    #pragma unroll
    for (int k = 0; k < 4; k++) {
        int r = r0 + k;
        float var = (q - s * s * (1.f / 49.f)) * (1.f / 48.f);
        float raw = rb[(ty0 + r) * Wn + tx0 + c];
        if (!(__float_as_uint(raw) >> 31))       // gate on (sign clear)
            acc += fabsf(var) * raw;             // raw >= 0 here
        if (k < 3) {
            s += s_hs[(r + 7) * HSS + c] - s_hs[r * HSS + c];
            q += s_hq[(r + 7) * HSS + c] - s_hq[r * HSS + c];
        }
    }

    acc = warpRed(acc);
    int lane = tid & 31, w = tid >> 5;
    if (lane == 0) sh[w] = acc;
    __syncthreads();
    if (w == 0) {
        acc = (lane < 8) ? sh[lane] : 0.f;
        acc = warpRed(acc);
        if (lane == 0)
            g_pS[(blockIdx.z * 16 + blockIdx.y) * 16 + blockIdx.x] = acc;
    }
}

// ---------------------------------------------------------------------------
// Final combine: per-image var^0.2 * S, summed. One block, 16 warps.
// ---------------------------------------------------------------------------
__global__ void k_final(float* out) {
    __shared__ double shd[16];
    int lane = threadIdx.x & 31, b = threadIdx.x >> 5;   // 512 threads
    double s = 0.0, q = 0.0, S = 0.0;
    for (int j = lane; j < 256; j += 32) {
        s += (double)g_psum[b * 256 + j];
        q += (double)g_psq [b * 256 + j];
        S += (double)g_pS  [b * 256 + j];
    }
    s = warpRedD(s); q = warpRedD(q); S = warpRedD(S);
    if (lane == 0) {
        double n   = (double)HWn;
        double var = (q - s * s / n) / (n - 1.0);
        shd[b] = pow(var, 0.2) * S;
    }
    __syncthreads();
    if (threadIdx.x == 0) {
        double tot = 0.0;
        #pragma unroll
        for (int i = 0; i < 16; i++) tot += shd[i];
        out[0] = (float)(tot / (double)((long long)Bn * 3 * HWn));
    }
}

extern "C" void kernel_launch(void* const* d_in, const int* in_sizes, int n_in,
                              void* d_out, int out_size) {
    const float* outp = (const float*)d_in[0];
    const float* emap = (const float*)d_in[1];
    const float* gtp  = (const float*)d_in[2];
    float* out = (float*)d_out;

    k_residual<<<RBLK, 256>>>(outp, emap, gtp);
    dim3 grid(Wn / TW, Hn / TH, Bn);
    k_localvar<<<grid, 256>>>();
    k_final<<<1, 512>>>(out);
}